// round 4
// baseline (speedup 1.0000x reference)
#include <cuda_runtime.h>
#include <cuda_bf16.h>
#include <cstdint>
#include <math.h>

#define T_TOK 4096
#define H_DIM 1024
#define F_DIM 2048
#define E_NUM 8
#define F2    (2 * F_DIM)

// ===================== helpers =====================
__device__ __forceinline__ uint32_t smem_u32(const void* p) {
    uint32_t a;
    asm("{ .reg .u64 t; cvta.to.shared.u64 t, %1; cvt.u32.u64 %0, t; }" : "=r"(a) : "l"(p));
    return a;
}
#define SW128(off) ((off) ^ (((off) >> 3) & 0x70))

__device__ __forceinline__ void cp_async16(uint32_t dst, const void* src, int srcBytes) {
    asm volatile("cp.async.cg.shared.global [%0], [%1], 16, %2;"
                 :: "r"(dst), "l"(src), "r"(srcBytes) : "memory");
}
#define CP_COMMIT() asm volatile("cp.async.commit_group;" ::: "memory")
#define CP_WAIT(n)  asm volatile("cp.async.wait_group %0;" :: "n"(n) : "memory")

__device__ __forceinline__ void ldsm4(uint32_t* r, uint32_t addr) {
    asm volatile("ldmatrix.sync.aligned.m8n8.x4.shared.b16 {%0,%1,%2,%3}, [%4];"
                 : "=r"(r[0]), "=r"(r[1]), "=r"(r[2]), "=r"(r[3]) : "r"(addr));
}

__device__ __forceinline__ void mma16816(float* d, const uint32_t* a, uint32_t b0, uint32_t b1) {
    asm volatile("mma.sync.aligned.m16n8k16.row.col.f32.bf16.bf16.f32 "
                 "{%0,%1,%2,%3}, {%4,%5,%6,%7}, {%8,%9}, {%0,%1,%2,%3};"
                 : "+f"(d[0]), "+f"(d[1]), "+f"(d[2]), "+f"(d[3])
                 : "r"(a[0]), "r"(a[1]), "r"(a[2]), "r"(a[3]), "r"(b0), "r"(b1));
}

__device__ __forceinline__ uint32_t pack_bf16(float x, float y) {
    __nv_bfloat162 t;
    t.x = __float2bfloat16(x);
    t.y = __float2bfloat16(y);
    return *(uint32_t*)&t;
}

// ===================== scratch (device globals; no allocs) =====================
__device__ __nv_bfloat16 g_x_hi [(size_t)T_TOK * H_DIM];
__device__ __nv_bfloat16 g_x_lo [(size_t)T_TOK * H_DIM];
__device__ __nv_bfloat16 g_sw1t_hi[(size_t)2 * F_DIM * H_DIM];
__device__ __nv_bfloat16 g_sw1t_lo[(size_t)2 * F_DIM * H_DIM];
__device__ __nv_bfloat16 g_ew1t_hi[(size_t)E_NUM * F_DIM * H_DIM];
__device__ __nv_bfloat16 g_ew1t_lo[(size_t)E_NUM * F_DIM * H_DIM];
__device__ __nv_bfloat16 g_sw2t_hi[(size_t)H_DIM * F2];
__device__ __nv_bfloat16 g_sw2t_lo[(size_t)H_DIM * F2];
__device__ __nv_bfloat16 g_ew2t_hi[(size_t)E_NUM * H_DIM * F_DIM];
__device__ __nv_bfloat16 g_ew2t_lo[(size_t)E_NUM * H_DIM * F_DIM];
__device__ __nv_bfloat16 g_hids_hi[(size_t)T_TOK * F2];
__device__ __nv_bfloat16 g_hids_lo[(size_t)T_TOK * F2];
__device__ __nv_bfloat16 g_hidr_hi[(size_t)2 * T_TOK * F_DIM];
__device__ __nv_bfloat16 g_hidr_lo[(size_t)2 * T_TOK * F_DIM];
__device__ float g_rout[(size_t)2 * T_TOK * H_DIM];
__device__ int g_counts[E_NUM];
__device__ int g_base[E_NUM];
__device__ int g_list[E_NUM * T_TOK];
__device__ int g_tok_e[2 * T_TOK];
__device__ int g_tok_slot[2 * T_TOK];

// ===================== router / base / combine =====================
__global__ void router_kernel(const float* __restrict__ x,
                              const float* __restrict__ rw,
                              const float* __restrict__ rb) {
    int warp = (blockIdx.x * blockDim.x + threadIdx.x) >> 5;
    int lane = threadIdx.x & 31;
    if (warp >= T_TOK) return;
    const float* xp = x + (long)warp * H_DIM;
    float acc[E_NUM];
#pragma unroll
    for (int e = 0; e < E_NUM; e++) acc[e] = 0.f;
    for (int h = lane; h < H_DIM; h += 32) {
        float xv = xp[h];
        const float* w = rw + (long)h * E_NUM;
#pragma unroll
        for (int e = 0; e < E_NUM; e++) acc[e] = fmaf(xv, w[e], acc[e]);
    }
#pragma unroll
    for (int e = 0; e < E_NUM; e++)
#pragma unroll
        for (int off = 16; off; off >>= 1)
            acc[e] += __shfl_xor_sync(0xFFFFFFFFu, acc[e], off);
    if (lane == 0) {
        float lg[E_NUM];
#pragma unroll
        for (int e = 0; e < E_NUM; e++) lg[e] = acc[e] + rb[e];
        int e0 = 0;
#pragma unroll
        for (int e = 1; e < E_NUM; e++) if (lg[e] > lg[e0]) e0 = e;
        int e1 = -1;
#pragma unroll
        for (int e = 0; e < E_NUM; e++) {
            if (e == e0) continue;
            if (e1 < 0 || lg[e] > lg[e1]) e1 = e;
        }
        int sel[2] = { e0, e1 };
        int t = warp;
#pragma unroll
        for (int k = 0; k < 2; k++) {
            int e = sel[k];
            int slot = atomicAdd(&g_counts[e], 1);
            g_list[e * T_TOK + slot] = t;
            g_tok_e[2 * t + k] = e;
            g_tok_slot[2 * t + k] = slot;
        }
    }
}

__global__ void base_kernel() {
    if (threadIdx.x == 0) {
        int s = 0;
#pragma unroll
        for (int e = 0; e < E_NUM; e++) { g_base[e] = s; s += g_counts[e]; }
    }
}

__global__ void combine_kernel(float* __restrict__ out) {
    int t = blockIdx.x;
    int e0 = g_tok_e[2 * t], e1 = g_tok_e[2 * t + 1];
    long r0 = (long)g_base[e0] + g_tok_slot[2 * t];
    long r1 = (long)g_base[e1] + g_tok_slot[2 * t + 1];
    const float4* p0 = (const float4*)g_rout + r0 * (H_DIM / 4);
    const float4* p1 = (const float4*)g_rout + r1 * (H_DIM / 4);
    float4* op = (float4*)out + (long)t * (H_DIM / 4);
    int i = threadIdx.x;
    float4 o = op[i], a = p0[i], b = p1[i];
    o.x += a.x + b.x; o.y += a.y + b.y; o.z += a.z + b.z; o.w += a.w + b.w;
    op[i] = o;
}

// ===================== fp32 -> bf16 hi/lo converters =====================
__global__ void split_kernel(const float* __restrict__ in,
                             __nv_bfloat16* __restrict__ hi,
                             __nv_bfloat16* __restrict__ lo, int n4) {
    int i = blockIdx.x * blockDim.x + threadIdx.x;
    if (i >= n4) return;
    float4 v = ((const float4*)in)[i];
    union { __nv_bfloat16 b[4]; uint2 u; } hb, lb;
    float vv[4] = { v.x, v.y, v.z, v.w };
#pragma unroll
    for (int u = 0; u < 4; u++) {
        __nv_bfloat16 h = __float2bfloat16(vv[u]);
        hb.b[u] = h;
        lb.b[u] = __float2bfloat16(vv[u] - __bfloat162float(h));
    }
    ((uint2*)hi)[i] = hb.u;
    ((uint2*)lo)[i] = lb.u;
}

// transpose + split: in [E][K][N] -> hi/lo at e*outEStride + n*ldOut + e*colOffE + k
__global__ void tsplit_kernel(const float* __restrict__ in,
                              __nv_bfloat16* __restrict__ hi,
                              __nv_bfloat16* __restrict__ lo,
                              int K, int N, long outEStride, int ldOut, int colOffE) {
    __shared__ float t[32][33];
    int e = blockIdx.z;
    int n0 = blockIdx.x * 32, k0 = blockIdx.y * 32;
    const float* src = in + (long)e * K * N;
    int tx = threadIdx.x, ty = threadIdx.y;
#pragma unroll
    for (int i = 0; i < 32; i += 8)
        t[ty + i][tx] = src[(long)(k0 + ty + i) * N + n0 + tx];
    __syncthreads();
    long obase = (long)e * outEStride + (long)e * colOffE;
#pragma unroll
    for (int i = 0; i < 32; i += 8) {
        float v = t[tx][ty + i];
        __nv_bfloat16 h = __float2bfloat16(v);
        long o = obase + (long)(n0 + ty + i) * ldOut + k0 + tx;
        hi[o] = h;
        lo[o] = __float2bfloat16(v - __bfloat162float(h));
    }
}

// ===================== mma.sync bf16x3 GEMM (fused hi/lo chunks) =====================
// C[M,N] = epi(A@B^T + bias) with A=Ahi+Alo, B=Bhi+Blo (lo*lo dropped).
// Tile 128x128, BK=32 per chunk; each chunk stages hi and lo side by side
// in 128B rows: bytes [0,64)=hi k0..31, [64,128)=lo k0..31.
// 3-stage cp.async ring: stage = A(16K) + B(16K) = 32KB.
#define STAGES 3
#define STAGE_BYTES 32768
#define DSMEM_BYTES (STAGES * STAGE_BYTES)

template<bool GELU, bool GATHER, bool EXPERT>
__global__ __launch_bounds__(256, 2)
void mma_gemm(const __nv_bfloat16* __restrict__ Ahi_,
              const __nv_bfloat16* __restrict__ Alo_,
              const __nv_bfloat16* __restrict__ Bhi_,
              const __nv_bfloat16* __restrict__ Blo_,
              const float* __restrict__ bias_,
              const float* __restrict__ bias2,
              __nv_bfloat16* __restrict__ Chi_,
              __nv_bfloat16* __restrict__ Clo_,
              float* __restrict__ Cf_,
              int M, int K, int ldc, long wStride, int bStride, int colOffZ)
{
    int z = blockIdx.z;
    const __nv_bfloat16* Bhi = Bhi_ + (long)z * wStride;
    const __nv_bfloat16* Blo = Blo_ + (long)z * wStride;
    const float* bias = bias_ + (long)z * bStride;
    int colOff = colOffZ * z;
    const __nv_bfloat16* Ahi = Ahi_;
    const __nv_bfloat16* Alo = Alo_;
    __nv_bfloat16* Chi = Chi_;
    __nv_bfloat16* Clo = Clo_;
    float* Cf = Cf_;
    const int* list = nullptr;
    if (EXPERT) {
        M = g_counts[z];
        long b = g_base[z];
        if (GATHER) list = g_list + (long)z * T_TOK;
        else { Ahi += b * (long)K; Alo += b * (long)K; }
        if (GELU) { Chi += b * (long)ldc; Clo += b * (long)ldc; }
        else Cf += b * (long)ldc;
    }
    int rowBase = blockIdx.x * 128;
    if (rowBase >= M) return;
    int colBase = blockIdx.y * 128;

    extern __shared__ char smem[];
    uint32_t sbase = smem_u32(smem);

    int tid = threadIdx.x;
    int wid = tid >> 5, lane = tid & 31;
    int warpM = wid & 3, warpN = wid >> 2;

    // loader metadata: 4 16B units each for A and B per stage
    uint32_t swoff[4]; int aRow[4], bRow[4], kel[4], aBytes[4]; bool hiSel[4];
#pragma unroll
    for (int i = 0; i < 4; i++) {
        int id = tid + i * 256;          // 0..1023
        int r = id >> 3;                 // tile row 0..127
        int c = id & 7;                  // 16B chunk within 128B row
        swoff[i] = SW128((uint32_t)(r * 128 + c * 16));
        kel[i] = (c & 3) * 8;            // element offset within 32-wide K chunk
        hiSel[i] = c < 4;
        int gR = rowBase + r;
        bool ok = gR < M;
        aBytes[i] = ok ? 16 : 0;
        aRow[i] = GATHER ? (ok ? list[gR] : 0) : (ok ? gR : 0);
        bRow[i] = colBase + r;
    }

    const int NC = K >> 5;               // 32-wide chunks

    auto issue = [&](int ci) {
        uint32_t sA = sbase + (ci % STAGES) * STAGE_BYTES;
        uint32_t sB = sA + 16384;
        int kbase = ci << 5;
#pragma unroll
        for (int i = 0; i < 4; i++) {
            const __nv_bfloat16* as = (hiSel[i] ? Ahi : Alo) + (long)aRow[i] * K + kbase + kel[i];
            cp_async16(sA + swoff[i], as, aBytes[i]);
            const __nv_bfloat16* bs = (hiSel[i] ? Bhi : Blo) + (long)bRow[i] * K + kbase + kel[i];
            cp_async16(sB + swoff[i], bs, 16);
        }
        CP_COMMIT();
    };

    float acc[2][8][4];
#pragma unroll
    for (int mi = 0; mi < 2; mi++)
#pragma unroll
        for (int nj = 0; nj < 8; nj++)
#pragma unroll
            for (int u = 0; u < 4; u++) acc[mi][nj][u] = 0.f;

    int lrow = lane & 15;
    int lc16 = (lane >> 4) * 16;

    issue(0); issue(1); issue(2);
    for (int ci = 0; ci < NC; ci++) {
        CP_WAIT(2);
        __syncthreads();
        uint32_t sA = sbase + (ci % STAGES) * STAGE_BYTES;
        uint32_t sB = sA + 16384;
#pragma unroll
        for (int ks = 0; ks < 2; ks++) {
            uint32_t ah[2][4], al[2][4];
#pragma unroll
            for (int mi = 0; mi < 2; mi++) {
                uint32_t r = (uint32_t)(warpM * 32 + mi * 16 + lrow) * 128 + ks * 32 + lc16;
                ldsm4(ah[mi], sA + SW128(r));
                ldsm4(al[mi], sA + SW128(r + 64));
            }
#pragma unroll
            for (int g = 0; g < 4; g++) {
                uint32_t r = (uint32_t)(warpN * 64 + g * 16 + lrow) * 128 + ks * 32 + lc16;
                uint32_t bh[4], bl[4];
                ldsm4(bh, sB + SW128(r));
#pragma unroll
                for (int mi = 0; mi < 2; mi++) {
                    mma16816(acc[mi][2 * g + 0], ah[mi], bh[0], bh[2]);
                    mma16816(acc[mi][2 * g + 1], ah[mi], bh[1], bh[3]);
                    mma16816(acc[mi][2 * g + 0], al[mi], bh[0], bh[2]);
                    mma16816(acc[mi][2 * g + 1], al[mi], bh[1], bh[3]);
                }
                ldsm4(bl, sB + SW128(r + 64));
#pragma unroll
                for (int mi = 0; mi < 2; mi++) {
                    mma16816(acc[mi][2 * g + 0], ah[mi], bl[0], bl[2]);
                    mma16816(acc[mi][2 * g + 1], ah[mi], bl[1], bl[3]);
                }
            }
        }
        __syncthreads();
        if (ci + STAGES < NC) issue(ci + STAGES);
        else CP_COMMIT();                // keep group count constant for CP_WAIT
    }

    // ---------------- epilogue ----------------
    int rw0 = rowBase + warpM * 32 + (lane >> 2);
    int cw0 = colBase + warpN * 64 + (lane & 3) * 2;
#pragma unroll
    for (int mi = 0; mi < 2; mi++) {
#pragma unroll
        for (int nj = 0; nj < 8; nj++) {
            int col = cw0 + nj * 8;
            float b0 = bias[col], b1 = bias[col + 1];
            if (bias2) { b0 += bias2[col]; b1 += bias2[col + 1]; }
#pragma unroll
            for (int h = 0; h < 2; h++) {
                int row = rw0 + mi * 16 + h * 8;
                if (row < M) {
                    float v0 = acc[mi][nj][2 * h + 0] + b0;
                    float v1 = acc[mi][nj][2 * h + 1] + b1;
                    long off = (long)row * ldc + colOff + col;
                    if (GELU) {
                        float g0 = 0.5f * v0 * (1.0f + erff(v0 * 0.70710678118654752f));
                        float g1 = 0.5f * v1 * (1.0f + erff(v1 * 0.70710678118654752f));
                        float h0 = __bfloat162float(__float2bfloat16(g0));
                        float h1 = __bfloat162float(__float2bfloat16(g1));
                        *(uint32_t*)(Chi + off) = pack_bf16(g0, g1);
                        *(uint32_t*)(Clo + off) = pack_bf16(g0 - h0, g1 - h1);
                    } else {
                        float2 v; v.x = v0; v.y = v1;
                        *(float2*)(Cf + off) = v;
                    }
                }
            }
        }
    }
}

// ===================== launch =====================
static void* symAddr(const void* sym) { void* p; cudaGetSymbolAddress(&p, sym); return p; }

extern "C" void kernel_launch(void* const* d_in, const int* in_sizes, int n_in,
                              void* d_out, int out_size)
{
    const float* x   = (const float*)d_in[0];
    const float* sw1 = (const float*)d_in[1];
    const float* sb1 = (const float*)d_in[2];
    const float* sw2 = (const float*)d_in[3];
    const float* sb2 = (const float*)d_in[4];
    const float* ew1 = (const float*)d_in[5];
    const float* eb1 = (const float*)d_in[6];
    const float* ew2 = (const float*)d_in[7];
    const float* eb2 = (const float*)d_in[8];
    const float* rw  = (const float*)d_in[9];
    const float* rb  = (const float*)d_in[10];
    float* out = (float*)d_out;

    __nv_bfloat16* x_hi   = (__nv_bfloat16*)symAddr(g_x_hi);
    __nv_bfloat16* x_lo   = (__nv_bfloat16*)symAddr(g_x_lo);
    __nv_bfloat16* sw1t_h = (__nv_bfloat16*)symAddr(g_sw1t_hi);
    __nv_bfloat16* sw1t_l = (__nv_bfloat16*)symAddr(g_sw1t_lo);
    __nv_bfloat16* ew1t_h = (__nv_bfloat16*)symAddr(g_ew1t_hi);
    __nv_bfloat16* ew1t_l = (__nv_bfloat16*)symAddr(g_ew1t_lo);
    __nv_bfloat16* sw2t_h = (__nv_bfloat16*)symAddr(g_sw2t_hi);
    __nv_bfloat16* sw2t_l = (__nv_bfloat16*)symAddr(g_sw2t_lo);
    __nv_bfloat16* ew2t_h = (__nv_bfloat16*)symAddr(g_ew2t_hi);
    __nv_bfloat16* ew2t_l = (__nv_bfloat16*)symAddr(g_ew2t_lo);
    __nv_bfloat16* hids_h = (__nv_bfloat16*)symAddr(g_hids_hi);
    __nv_bfloat16* hids_l = (__nv_bfloat16*)symAddr(g_hids_lo);
    __nv_bfloat16* hidr_h = (__nv_bfloat16*)symAddr(g_hidr_hi);
    __nv_bfloat16* hidr_l = (__nv_bfloat16*)symAddr(g_hidr_lo);
    float* rout = (float*)symAddr(g_rout);
    int* counts = (int*)symAddr(g_counts);

    cudaFuncSetAttribute(mma_gemm<true, false, false>, cudaFuncAttributeMaxDynamicSharedMemorySize, DSMEM_BYTES);
    cudaFuncSetAttribute(mma_gemm<true, true,  true>,  cudaFuncAttributeMaxDynamicSharedMemorySize, DSMEM_BYTES);
    cudaFuncSetAttribute(mma_gemm<false, false, false>, cudaFuncAttributeMaxDynamicSharedMemorySize, DSMEM_BYTES);
    cudaFuncSetAttribute(mma_gemm<false, false, true>, cudaFuncAttributeMaxDynamicSharedMemorySize, DSMEM_BYTES);

    cudaMemsetAsync(counts, 0, E_NUM * sizeof(int));
    router_kernel<<<T_TOK / 4, 128>>>(x, rw, rb);
    base_kernel<<<1, 32>>>();

    // conversions
    split_kernel<<<(T_TOK * H_DIM / 4 + 255) / 256, 256>>>(x, x_hi, x_lo, T_TOK * H_DIM / 4);
    tsplit_kernel<<<dim3(F_DIM / 32, H_DIM / 32, 2), dim3(32, 8)>>>(
        sw1, sw1t_h, sw1t_l, H_DIM, F_DIM, (long)F_DIM * H_DIM, H_DIM, 0);
    tsplit_kernel<<<dim3(F_DIM / 32, H_DIM / 32, E_NUM), dim3(32, 8)>>>(
        ew1, ew1t_h, ew1t_l, H_DIM, F_DIM, (long)F_DIM * H_DIM, H_DIM, 0);
    tsplit_kernel<<<dim3(H_DIM / 32, F_DIM / 32, 2), dim3(32, 8)>>>(
        sw2, sw2t_h, sw2t_l, F_DIM, H_DIM, 0, F2, F_DIM);
    tsplit_kernel<<<dim3(H_DIM / 32, F_DIM / 32, E_NUM), dim3(32, 8)>>>(
        ew2, ew2t_h, ew2t_l, F_DIM, H_DIM, (long)H_DIM * F_DIM, F_DIM, 0);

    // shared GEMM1: hid_s[:, z*F:(z+1)*F] = gelu(x @ sw1[z] + sb1[z])
    mma_gemm<true, false, false><<<dim3(T_TOK / 128, F_DIM / 128, 2), 256, DSMEM_BYTES>>>(
        x_hi, x_lo, sw1t_h, sw1t_l, sb1, nullptr, hids_h, hids_l, nullptr,
        T_TOK, H_DIM, F2, (long)F_DIM * H_DIM, F_DIM, F_DIM);

    // routed GEMM1: per-expert gathered rows of x
    mma_gemm<true, true, true><<<dim3(T_TOK / 128, F_DIM / 128, E_NUM), 256, DSMEM_BYTES>>>(
        x_hi, x_lo, ew1t_h, ew1t_l, eb1, nullptr, hidr_h, hidr_l, nullptr,
        0, H_DIM, F_DIM, (long)F_DIM * H_DIM, F_DIM, 0);

    // shared GEMM2: out = hid_s @ [sw2_0; sw2_1] + sb2_0 + sb2_1
    mma_gemm<false, false, false><<<dim3(T_TOK / 128, H_DIM / 128, 1), 256, DSMEM_BYTES>>>(
        hids_h, hids_l, sw2t_h, sw2t_l, sb2, sb2 + H_DIM, nullptr, nullptr, out,
        T_TOK, F2, H_DIM, 0, 0, 0);

    // routed GEMM2: rout = hid_r @ ew2[e] + eb2[e]
    mma_gemm<false, false, true><<<dim3(T_TOK / 128, H_DIM / 128, E_NUM), 256, DSMEM_BYTES>>>(
        hidr_h, hidr_l, ew2t_h, ew2t_l, eb2, nullptr, nullptr, nullptr, rout,
        0, F_DIM, H_DIM, (long)H_DIM * F_DIM, H_DIM, 0);

    combine_kernel<<<T_TOK, 256>>>(out);
}